// round 13
// baseline (speedup 1.0000x reference)
#include <cuda_runtime.h>
#include <math.h>

// Problem constants
#define B    32
#define L    2048
#define E    512
#define H    512
#define V    32000
#define D2H  1024          // 2*H
#define SPLITS 8           // L split for k1 reduction (256 rows per block)

// Output layout (fp32): logp[32000] | h_new[32768] | attn_weights[65536]
#define OUT_LOGP  0
#define OUT_HNEW  32000
#define OUT_ATTN  64768

// GRU GEMM geometry: rows = 2 cells * 3 gates * 512 = 3072, K = 1024(ih) + 512(hh)
#define NROWS 3072
#define ROWT  64            // rows per block tile
#define KPS   64            // K per split (ih: 16 splits, hh: 8 splits)

// -------------------- scratch --------------------
__device__ float4 g_partial[B * SPLITS * (D2H / 4)];   // 1 MB
__device__ float  g_cT[D2H * B];                       // c transposed [k][b]
__device__ float  g_gi[NROWS * B];                     // accumulated gi (RED)
__device__ float  g_gh[NROWS * B];                     // accumulated gh (RED)
__device__ float  g_logits[V];
__device__ float2 g_lse[32];
// fast path (batch 31 only)
__device__ float4 g_p31[128 * 256];
__device__ float  g_c31[D2H];
__device__ float2 g_g31[NROWS];
__device__ float  g_colast[D2H];

// ==================== BIG PATH ====================

// -------------------- K0: zero RED accumulators --------------------
__global__ void k0_zero()
{
    int idx = blockIdx.x * 256 + threadIdx.x;          // 0..49151
    if (idx < 24576) ((float4*)g_gi)[idx]         = make_float4(0.f, 0.f, 0.f, 0.f);
    else             ((float4*)g_gh)[idx - 24576] = make_float4(0.f, 0.f, 0.f, 0.f);
}

// -------------------- K1: partial reduce of encoder_out over L (+ attn fill) --------------------
// grid (SPLITS=8, B), 256 threads; each block streams 256 L-rows.
__global__ void k1_reduce(const float4* __restrict__ enc, float* __restrict__ out)
{
    int s = blockIdx.x, b = blockIdx.y, t = threadIdx.x;
    int l0 = s * (L / SPLITS);
    float4 acc = make_float4(0.f, 0.f, 0.f, 0.f);
    const float4* base = enc + (size_t)(b * L + l0) * (D2H / 4) + t;
#pragma unroll 8
    for (int l = 0; l < L / SPLITS; ++l) {
        float4 v = base[(size_t)l * (D2H / 4)];
        acc.x += v.x; acc.y += v.y; acc.z += v.z; acc.w += v.w;
    }
    g_partial[(b * SPLITS + s) * (D2H / 4) + t] = acc;

    // constant attn_weights fill: 256 blocks x 64 float4 = 16384 float4
    if (t < 64) {
        int fid = b * SPLITS + s;
        const float w = 1.0f / (float)L;
        ((float4*)(out + OUT_ATTN))[fid * 64 + t] = make_float4(w, w, w, w);
    }
}

// -------------------- K2: finalize c = relu(mean), store transposed --------------------
// 64 blocks x 128 threads; one thread per (b, float4-col)
__global__ void k2_finalize()
{
    int idx = blockIdx.x * 128 + threadIdx.x;   // 0..8191
    int b   = idx >> 8;
    int t   = idx & 255;

    float4 v[SPLITS];
#pragma unroll
    for (int s = 0; s < SPLITS; ++s)
        v[s] = g_partial[(b * SPLITS + s) * (D2H / 4) + t];

    float4 acc = make_float4(0.f, 0.f, 0.f, 0.f);
#pragma unroll
    for (int s = 0; s < SPLITS; ++s) {
        acc.x += v[s].x; acc.y += v[s].y; acc.z += v[s].z; acc.w += v[s].w;
    }
    const float inv = 1.0f / (float)L;
    float vals[4] = { acc.x * inv, acc.y * inv, acc.z * inv, acc.w * inv };
#pragma unroll
    for (int i = 0; i < 4; ++i) {
        float c = vals[i] > 0.f ? vals[i] : 0.f;
        g_cT[(4 * t + i) * B + b] = c;
    }
}

// -------------------- K3a: split-K register-tiled GEMM, swizzled smem, RED epilogue ------
// Launched twice: hh (split0=16, nspl=8) and ih (split0=0, nspl=16).
// Swizzle: element (k, col) lives at [k][col ^ (k & 0x1C)].
__global__ void k3a_gemm(int split0, int nspl,
                         const float* __restrict__ h,
                         const float* __restrict__ Wih_f, const float* __restrict__ Whh_f,
                         const float* __restrict__ Wih_b, const float* __restrict__ Whh_b)
{
    int tile  = blockIdx.x / nspl;
    int split = split0 + (blockIdx.x % nspl);
    int R0    = tile * ROWT;
    int cell  = (R0 >= 1536) ? 1 : 0;
    int gr0   = R0 - cell * 1536;

    const bool   hh   = (split >= 16);
    const float* W    = hh ? (cell ? Whh_b : Whh_f) : (cell ? Wih_b : Wih_f);
    const int    ldw  = hh ? H : D2H;
    const int    koff = hh ? (split - 16) * KPS : split * KPS;

    __shared__ float sW[32 * 64];      // [k][row^swz]
    __shared__ float sX[32 * 32];      // [k][b^swz]

    int tid = threadIdx.x;
    int tx  = tid & 7;
    int ty  = tid >> 3;

    float acc[4][4];
#pragma unroll
    for (int i = 0; i < 4; ++i)
#pragma unroll
        for (int j = 0; j < 4; ++j) acc[i][j] = 0.f;

    const float4* H4  = (const float4*)(h + (size_t)cell * B * H);
    const float4* cT4 = (const float4*)g_cT;

#pragma unroll
    for (int kt = 0; kt < KPS; kt += 32) {
#pragma unroll
        for (int i = 0; i < 4; ++i) {
            int idx = tid + i * 128;
            int row = idx >> 3, kg = idx & 7;
            const float4* wr = (const float4*)(W + (size_t)(gr0 + row) * ldw + koff + kt);
            float4 w = wr[kg];
            int k0 = 4 * kg;
            int c  = row ^ k0;
            sW[(k0 + 0) * 64 + c] = w.x;
            sW[(k0 + 1) * 64 + c] = w.y;
            sW[(k0 + 2) * 64 + c] = w.z;
            sW[(k0 + 3) * 64 + c] = w.w;
        }
        if (!hh) {
#pragma unroll
            for (int i = 0; i < 2; ++i) {
                int idx = tid + i * 128;
                int k = idx >> 3, bg = idx & 7;
                int s = k & 0x1C;
                *(float4*)&sX[k * 32 + ((4 * bg) ^ s)] =
                    cT4[(size_t)(koff + kt + k) * 8 + bg];
            }
        } else {
#pragma unroll
            for (int i = 0; i < 2; ++i) {
                int idx = tid + i * 128;
                int b = idx >> 3, kg = idx & 7;
                float4 hv = H4[(size_t)b * (H / 4) + ((koff + kt) >> 2) + kg];
                int k0 = 4 * kg;
                int c  = b ^ k0;
                sX[(k0 + 0) * 32 + c] = hv.x;
                sX[(k0 + 1) * 32 + c] = hv.y;
                sX[(k0 + 2) * 32 + c] = hv.z;
                sX[(k0 + 3) * 32 + c] = hv.w;
            }
        }
        __syncthreads();

#pragma unroll
        for (int k = 0; k < 32; ++k) {
            int s = k & 0x1C;
            float4 a = *(const float4*)&sX[k * 32 + ((4 * tx) ^ s)];
            float4 w = *(const float4*)&sW[k * 64 + ((4 * ty) ^ s)];
            acc[0][0] += a.x * w.x; acc[0][1] += a.x * w.y; acc[0][2] += a.x * w.z; acc[0][3] += a.x * w.w;
            acc[1][0] += a.y * w.x; acc[1][1] += a.y * w.y; acc[1][2] += a.y * w.z; acc[1][3] += a.y * w.w;
            acc[2][0] += a.z * w.x; acc[2][1] += a.z * w.y; acc[2][2] += a.z * w.z; acc[2][3] += a.z * w.w;
            acc[3][0] += a.w * w.x; acc[3][1] += a.w * w.y; acc[3][2] += a.w * w.z; acc[3][3] += a.w * w.w;
        }
        __syncthreads();
    }

    float* gdst = hh ? g_gh : g_gi;
#pragma unroll
    for (int j = 0; j < 4; ++j)
#pragma unroll
        for (int i = 0; i < 4; ++i)
            atomicAdd(&gdst[(R0 + 4 * ty + j) * B + 4 * tx + i], acc[i][j]);
}

// -------------------- K3b2: gate math + nonlinearity (h_new only) --------------------
__device__ __forceinline__ float sigmoidf_(float x) { return 1.0f / (1.0f + expf(-x)); }

__global__ void k3b2_gate(const float* __restrict__ h,
                          const float* __restrict__ bih_f, const float* __restrict__ bhh_f,
                          const float* __restrict__ bih_b, const float* __restrict__ bhh_b,
                          float* __restrict__ out)
{
    int idx  = blockIdx.x * 256 + threadIdx.x;
    int b    = idx & 31;
    int j    = (idx >> 5) & 511;
    int cell = idx >> 14;

    const float* bih = cell ? bih_b : bih_f;
    const float* bhh = cell ? bhh_b : bhh_f;
    int Rb = cell * 1536;

    float Gir = g_gi[(Rb +        j) * B + b] + bih[j];
    float Ghr = g_gh[(Rb +        j) * B + b] + bhh[j];
    float Giz = g_gi[(Rb +  512 + j) * B + b] + bih[512 + j];
    float Ghz = g_gh[(Rb +  512 + j) * B + b] + bhh[512 + j];
    float Gin = g_gi[(Rb + 1024 + j) * B + b] + bih[1024 + j];
    float Ghn = g_gh[(Rb + 1024 + j) * B + b] + bhh[1024 + j];

    float hprev = h[(size_t)cell * B * H + b * H + j];
    float r = sigmoidf_(Gir + Ghr);
    float z = sigmoidf_(Giz + Ghz);
    float n = tanhf(Gin + r * Ghn);
    float hn = (1.0f - z) * n + z * hprev;

    out[OUT_HNEW + cell * B * H + b * H + j] = hn;
}

// ==================== FAST PATH (batch 31 -> logits -> logp) ====================

__global__ void kf1_reduce31(const float4* __restrict__ enc)
{
    int s = blockIdx.x, t = threadIdx.x;
    const float4* base = enc + ((size_t)(31 * L + s * 16)) * (D2H / 4) + t;
    float4 acc = make_float4(0.f, 0.f, 0.f, 0.f);
#pragma unroll
    for (int l = 0; l < 16; ++l) {
        float4 v = base[(size_t)l * (D2H / 4)];
        acc.x += v.x; acc.y += v.y; acc.z += v.z; acc.w += v.w;
    }
    g_p31[s * 256 + t] = acc;
}

__global__ void kf1b_c31()
{
    int t = threadIdx.x;
    float4 acc = make_float4(0.f, 0.f, 0.f, 0.f);
#pragma unroll 8
    for (int s = 0; s < 128; ++s) {
        float4 v = g_p31[s * 256 + t];
        acc.x += v.x; acc.y += v.y; acc.z += v.z; acc.w += v.w;
    }
    const float inv = 1.0f / (float)L;
    acc.x = fmaxf(acc.x * inv, 0.f);
    acc.y = fmaxf(acc.y * inv, 0.f);
    acc.z = fmaxf(acc.z * inv, 0.f);
    acc.w = fmaxf(acc.w * inv, 0.f);
    ((float4*)g_c31)[t] = acc;
}

__global__ void kf2a_dots31(const float* __restrict__ h,
                            const float* __restrict__ Wih_f, const float* __restrict__ Whh_f,
                            const float* __restrict__ Wih_b, const float* __restrict__ Whh_b)
{
    int gwid = (blockIdx.x * 256 + threadIdx.x) >> 5;
    int lane = threadIdx.x & 31;
    int p    = gwid & 1;
    int R    = gwid >> 1;
    int cell = (R >= 1536) ? 1 : 0;
    int gr   = R - cell * 1536;

    float acc = 0.f;
    if (!p) {
        const float4* w = (const float4*)((cell ? Wih_b : Wih_f) + (size_t)gr * D2H);
        const float4* x = (const float4*)g_c31;
#pragma unroll
        for (int i = 0; i < 8; ++i) {
            float4 a = w[lane + 32 * i];
            float4 c = x[lane + 32 * i];
            acc += a.x * c.x + a.y * c.y + a.z * c.z + a.w * c.w;
        }
    } else {
        const float4* w = (const float4*)((cell ? Whh_b : Whh_f) + (size_t)gr * H);
        const float4* x = (const float4*)(h + (size_t)cell * B * H + 31 * H);
#pragma unroll
        for (int i = 0; i < 4; ++i) {
            float4 a = w[lane + 32 * i];
            float4 c = x[lane + 32 * i];
            acc += a.x * c.x + a.y * c.y + a.z * c.z + a.w * c.w;
        }
    }
#pragma unroll
    for (int o = 16; o; o >>= 1) acc += __shfl_xor_sync(0xFFFFFFFFu, acc, o);
    if (lane == 0) {
        if (!p) g_g31[R].x = acc;
        else    g_g31[R].y = acc;
    }
}

__global__ void kf2b_gate31(const float* __restrict__ h,
                            const float* __restrict__ bih_f, const float* __restrict__ bhh_f,
                            const float* __restrict__ bih_b, const float* __restrict__ bhh_b)
{
    int tid  = threadIdx.x;
    int cell = tid >> 9;
    int j    = tid & 511;

    const float* bih = cell ? bih_b : bih_f;
    const float* bhh = cell ? bhh_b : bhh_f;
    int Rb = cell * 1536;

    float2 pr = g_g31[Rb +        j];
    float2 pz = g_g31[Rb +  512 + j];
    float2 pn = g_g31[Rb + 1024 + j];

    float h31 = h[(size_t)cell * B * H + 31 * H + j];
    float r = sigmoidf_(pr.x + bih[j]        + pr.y + bhh[j]);
    float z = sigmoidf_(pz.x + bih[512 + j]  + pz.y + bhh[512 + j]);
    float n = tanhf(pn.x + bih[1024 + j] + r * (pn.y + bhh[1024 + j]));
    g_colast[cell * H + j] = (1.0f - z) * n + z * h31;
}

__global__ void k4_logits(const float4* __restrict__ outW, const float* __restrict__ outb)
{
    __shared__ float4 sc[D2H / 4];
    int tid = threadIdx.x;
    sc[tid] = ((const float4*)g_colast)[tid];
    __syncthreads();

    int warp = tid >> 5, lane = tid & 31;
    int v = blockIdx.x * 8 + warp;
    const float4* wrow = outW + (size_t)v * (D2H / 4);
    float acc = 0.f;
#pragma unroll
    for (int i = 0; i < 8; ++i) {
        float4 w = wrow[lane + 32 * i];
        float4 c = sc[lane + 32 * i];
        acc += w.x * c.x + w.y * c.y + w.z * c.z + w.w * c.w;
    }
#pragma unroll
    for (int o = 16; o; o >>= 1) acc += __shfl_xor_sync(0xFFFFFFFFu, acc, o);
    if (lane == 0) g_logits[v] = acc + outb[v];
}

__global__ void k5a_partial()
{
    const float4* L4 = (const float4*)g_logits;
    int tid = threadIdx.x;
    __shared__ float red[8];

    float m = -1e30f;
    for (int i = blockIdx.x * 256 + tid; i < V / 4; i += 32 * 256) {
        float4 v = L4[i];
        m = fmaxf(m, fmaxf(fmaxf(v.x, v.y), fmaxf(v.z, v.w)));
    }
#pragma unroll
    for (int o = 16; o; o >>= 1) m = fmaxf(m, __shfl_xor_sync(0xFFFFFFFFu, m, o));
    if ((tid & 31) == 0) red[tid >> 5] = m;
    __syncthreads();
    float bm = fmaxf(fmaxf(fmaxf(red[0], red[1]), fmaxf(red[2], red[3])),
                     fmaxf(fmaxf(red[4], red[5]), fmaxf(red[6], red[7])));
    __syncthreads();

    float s = 0.f;
    for (int i = blockIdx.x * 256 + tid; i < V / 4; i += 32 * 256) {
        float4 v = L4[i];
        s += expf(v.x - bm) + expf(v.y - bm) + expf(v.z - bm) + expf(v.w - bm);
    }
#pragma unroll
    for (int o = 16; o; o >>= 1) s += __shfl_xor_sync(0xFFFFFFFFu, s, o);
    if ((tid & 31) == 0) red[tid >> 5] = s;
    __syncthreads();
    if (tid == 0) {
        float bs = red[0] + red[1] + red[2] + red[3] + red[4] + red[5] + red[6] + red[7];
        g_lse[blockIdx.x] = make_float2(bm, bs);
    }
}

__global__ void k5b_write(float* __restrict__ out)
{
    float M = -1e30f;
#pragma unroll
    for (int i = 0; i < 32; ++i) M = fmaxf(M, g_lse[i].x);
    float S = 0.f;
#pragma unroll
    for (int i = 0; i < 32; ++i) { float2 p = g_lse[i]; S += p.y * expf(p.x - M); }
    float lse = M + logf(S);

    const float4* L4 = (const float4*)g_logits;
    float4* O4 = (float4*)(out + OUT_LOGP);
    for (int i = blockIdx.x * 256 + threadIdx.x; i < V / 4; i += 32 * 256) {
        float4 v = L4[i];
        v.x -= lse; v.y -= lse; v.z -= lse; v.w -= lse;
        O4[i] = v;
    }
}

// -------------------- launch: 3 worker streams, event fork/join --------------------
extern "C" void kernel_launch(void* const* d_in, const int* in_sizes, int n_in,
                              void* d_out, int out_size)
{
    (void)in_sizes; (void)n_in; (void)out_size;
    const float* h_in   = (const float*)d_in[1];
    const float* enc    = (const float*)d_in[2];
    const float* Wih_f  = (const float*)d_in[6];
    const float* Whh_f  = (const float*)d_in[7];
    const float* bih_f  = (const float*)d_in[8];
    const float* bhh_f  = (const float*)d_in[9];
    const float* Wih_b  = (const float*)d_in[10];
    const float* Whh_b  = (const float*)d_in[11];
    const float* bih_b  = (const float*)d_in[12];
    const float* bhh_b  = (const float*)d_in[13];
    const float* outW   = (const float*)d_in[14];
    const float* outb   = (const float*)d_in[15];
    float* out = (float*)d_out;

    cudaStream_t s2, s3, s4;
    cudaStreamCreateWithFlags(&s2, cudaStreamNonBlocking);
    cudaStreamCreateWithFlags(&s3, cudaStreamNonBlocking);
    cudaStreamCreateWithFlags(&s4, cudaStreamNonBlocking);
    cudaEvent_t eF, e2, e3, eZ, eHH;
    cudaEventCreateWithFlags(&eF,  cudaEventDisableTiming);
    cudaEventCreateWithFlags(&e2,  cudaEventDisableTiming);
    cudaEventCreateWithFlags(&e3,  cudaEventDisableTiming);
    cudaEventCreateWithFlags(&eZ,  cudaEventDisableTiming);
    cudaEventCreateWithFlags(&eHH, cudaEventDisableTiming);

    // fork off the capture stream; stream 0 carries no kernels
    cudaEventRecord(eF, 0);
    cudaStreamWaitEvent(s2, eF, 0);
    cudaStreamWaitEvent(s3, eF, 0);
    cudaStreamWaitEvent(s4, eF, 0);

    // ---- s4: zero (eZ) + hh GEMM (eHH) — runs under k1 ----
    k0_zero<<<192, 256, 0, s4>>>();
    cudaEventRecord(eZ, s4);                       // zeroing done -> ih atomics may start
    k3a_gemm<<<48 * 8, 128, 0, s4>>>(16, 8, h_in, Wih_f, Whh_f, Wih_b, Whh_b);
    cudaEventRecord(eHH, s4);                      // hh results ready -> gates may read

    // ---- s2: big path (attn fill + c + ih GEMM + gates) ----
    k1_reduce<<<dim3(SPLITS, B), 256, 0, s2>>>((const float4*)enc, out);
    k2_finalize<<<64, 128, 0, s2>>>();
    cudaStreamWaitEvent(s2, eZ, 0);                // only the zeroing gates ih
    k3a_gemm<<<48 * 16, 128, 0, s2>>>(0, 16, h_in, Wih_f, Whh_f, Wih_b, Whh_b);
    cudaStreamWaitEvent(s2, eHH, 0);               // hh must be complete before gates
    k3b2_gate<<<(2 * B * H) / 256, 256, 0, s2>>>(h_in, bih_f, bhh_f, bih_b, bhh_b, out);
    cudaEventRecord(e2, s2);

    // ---- s3: fast path (batch 31 -> logp) ----
    kf1_reduce31<<<128, 256, 0, s3>>>((const float4*)enc);
    kf1b_c31<<<1, 256, 0, s3>>>();
    kf2a_dots31<<<768, 256, 0, s3>>>(h_in, Wih_f, Whh_f, Wih_b, Whh_b);
    kf2b_gate31<<<1, 1024, 0, s3>>>(h_in, bih_f, bhh_f, bih_b, bhh_b);
    k4_logits<<<V / 8, 256, 0, s3>>>((const float4*)outW, outb);
    k5a_partial<<<32, 256, 0, s3>>>();
    k5b_write<<<32, 256, 0, s3>>>(out);
    cudaEventRecord(e3, s3);

    // join
    cudaStreamWaitEvent(0, e2, 0);
    cudaStreamWaitEvent(0, e3, 0);

    cudaEventDestroy(eF);
    cudaEventDestroy(e2);
    cudaEventDestroy(e3);
    cudaEventDestroy(eZ);
    cudaEventDestroy(eHH);
    cudaStreamDestroy(s2);
    cudaStreamDestroy(s3);
    cudaStreamDestroy(s4);
}

// round 14
// speedup vs baseline: 1.0006x; 1.0006x over previous
#include <cuda_runtime.h>
#include <math.h>

// Problem constants
#define B    32
#define L    2048
#define E    512
#define H    512
#define V    32000
#define D2H  1024          // 2*H
#define SPLITS 8           // L split for k1 reduction (256 rows per block)

// Output layout (fp32): logp[32000] | h_new[32768] | attn_weights[65536]
#define OUT_LOGP  0
#define OUT_HNEW  32000
#define OUT_ATTN  64768

// GRU GEMM geometry: rows = 2 cells * 3 gates * 512 = 3072, K = 1024(ih) + 512(hh)
#define NROWS 3072
#define ROWT  64            // rows per block tile
#define KSPL  24            // splits: 0..15 = ih (64 cols each), 16..23 = hh (64 cols each)
#define KPS   64            // K per split

// -------------------- scratch --------------------
__device__ float  g_cacc[D2H * B];       // c accumulator, [k][b] layout (RED from k1)
__device__ float  g_gi[NROWS * B];       // accumulated gi (RED)
__device__ float  g_gh[NROWS * B];       // accumulated gh (RED)
__device__ float  g_colast[D2H];         // [h_f[31], h_b[31]]
__device__ float  g_logits[V];
__device__ float2 g_lse[32];             // per-block (max, sumexp)

// -------------------- K0: zero all RED accumulators --------------------
// g_gi: 24576 float4, g_gh: 24576 float4, g_cacc: 8192 float4  => 57344 float4
__global__ void k0_zero()
{
    int idx = blockIdx.x * 256 + threadIdx.x;          // 225*256 = 57600 threads
    const float4 z = make_float4(0.f, 0.f, 0.f, 0.f);
    if      (idx < 24576) ((float4*)g_gi)[idx]          = z;
    else if (idx < 49152) ((float4*)g_gh)[idx - 24576]  = z;
    else if (idx < 57344) ((float4*)g_cacc)[idx - 49152] = z;
}

// -------------------- K1: reduce encoder_out over L -> atomic c accumulate (+ attn fill) ----
// grid (SPLITS=8, B), 256 threads; each block streams 256 contiguous L-rows.
__global__ void k1_reduce(const float4* __restrict__ enc, float* __restrict__ out)
{
    int s = blockIdx.x, b = blockIdx.y, t = threadIdx.x;
    int l0 = s * (L / SPLITS);
    float4 acc = make_float4(0.f, 0.f, 0.f, 0.f);
    const float4* base = enc + (size_t)(b * L + l0) * (D2H / 4) + t;
#pragma unroll 8
    for (int l = 0; l < L / SPLITS; ++l) {
        float4 v = base[(size_t)l * (D2H / 4)];
        acc.x += v.x; acc.y += v.y; acc.z += v.z; acc.w += v.w;
    }
    // accumulate into transposed c accumulator [k][b]
    atomicAdd(&g_cacc[(4 * t + 0) * B + b], acc.x);
    atomicAdd(&g_cacc[(4 * t + 1) * B + b], acc.y);
    atomicAdd(&g_cacc[(4 * t + 2) * B + b], acc.z);
    atomicAdd(&g_cacc[(4 * t + 3) * B + b], acc.w);

    // constant attn_weights fill: 256 blocks x 64 float4 = 16384 float4
    if (t < 64) {
        int fid = b * SPLITS + s;
        const float w = 1.0f / (float)L;
        ((float4*)(out + OUT_ATTN))[fid * 64 + t] = make_float4(w, w, w, w);
    }
}

// -------------------- K3a: split-K register-tiled GEMM, swizzled smem, RED epilogue ------
// One launch: 48 row-tiles * 24 splits = 1152 blocks, 128 threads.
// ih splits read g_cacc with inline relu(x/L); hh splits read h.
// Swizzle: element (k, col) lives at [k][col ^ (k & 0x1C)].
__global__ void k3a_gemm(const float* __restrict__ h,
                         const float* __restrict__ Wih_f, const float* __restrict__ Whh_f,
                         const float* __restrict__ Wih_b, const float* __restrict__ Whh_b)
{
    int tile  = blockIdx.x / KSPL;
    int split = blockIdx.x % KSPL;
    int R0    = tile * ROWT;
    int cell  = (R0 >= 1536) ? 1 : 0;
    int gr0   = R0 - cell * 1536;

    const bool   hh   = (split >= 16);
    const float* W    = hh ? (cell ? Whh_b : Whh_f) : (cell ? Wih_b : Wih_f);
    const int    ldw  = hh ? H : D2H;
    const int    koff = hh ? (split - 16) * KPS : split * KPS;

    __shared__ float sW[32 * 64];      // [k][row^swz]
    __shared__ float sX[32 * 32];      // [k][b^swz]

    int tid = threadIdx.x;
    int tx  = tid & 7;
    int ty  = tid >> 3;

    float acc[4][4];
#pragma unroll
    for (int i = 0; i < 4; ++i)
#pragma unroll
        for (int j = 0; j < 4; ++j) acc[i][j] = 0.f;

    const float4* H4  = (const float4*)(h + (size_t)cell * B * H);
    const float4* cA4 = (const float4*)g_cacc;
    const float   invL = 1.0f / (float)L;

#pragma unroll
    for (int kt = 0; kt < KPS; kt += 32) {
        // --- W tile: 64 rows x 32 k, swizzled transpose ---
#pragma unroll
        for (int i = 0; i < 4; ++i) {
            int idx = tid + i * 128;
            int row = idx >> 3, kg = idx & 7;
            const float4* wr = (const float4*)(W + (size_t)(gr0 + row) * ldw + koff + kt);
            float4 w = wr[kg];
            int k0 = 4 * kg;
            int c  = row ^ k0;
            sW[(k0 + 0) * 64 + c] = w.x;
            sW[(k0 + 1) * 64 + c] = w.y;
            sW[(k0 + 2) * 64 + c] = w.z;
            sW[(k0 + 3) * 64 + c] = w.w;
        }
        // --- X tile ---
        if (!hh) {
#pragma unroll
            for (int i = 0; i < 2; ++i) {
                int idx = tid + i * 128;
                int k = idx >> 3, bg = idx & 7;
                float4 v = cA4[(size_t)(koff + kt + k) * 8 + bg];
                v.x = fmaxf(v.x * invL, 0.f);
                v.y = fmaxf(v.y * invL, 0.f);
                v.z = fmaxf(v.z * invL, 0.f);
                v.w = fmaxf(v.w * invL, 0.f);
                int s = k & 0x1C;
                *(float4*)&sX[k * 32 + ((4 * bg) ^ s)] = v;
            }
        } else {
#pragma unroll
            for (int i = 0; i < 2; ++i) {
                int idx = tid + i * 128;
                int b = idx >> 3, kg = idx & 7;
                float4 hv = H4[(size_t)b * (H / 4) + ((koff + kt) >> 2) + kg];
                int k0 = 4 * kg;
                int c  = b ^ k0;
                sX[(k0 + 0) * 32 + c] = hv.x;
                sX[(k0 + 1) * 32 + c] = hv.y;
                sX[(k0 + 2) * 32 + c] = hv.z;
                sX[(k0 + 3) * 32 + c] = hv.w;
            }
        }
        __syncthreads();

#pragma unroll
        for (int k = 0; k < 32; ++k) {
            int s = k & 0x1C;
            float4 a = *(const float4*)&sX[k * 32 + ((4 * tx) ^ s)];
            float4 w = *(const float4*)&sW[k * 64 + ((4 * ty) ^ s)];
            acc[0][0] += a.x * w.x; acc[0][1] += a.x * w.y; acc[0][2] += a.x * w.z; acc[0][3] += a.x * w.w;
            acc[1][0] += a.y * w.x; acc[1][1] += a.y * w.y; acc[1][2] += a.y * w.z; acc[1][3] += a.y * w.w;
            acc[2][0] += a.z * w.x; acc[2][1] += a.z * w.y; acc[2][2] += a.z * w.z; acc[2][3] += a.z * w.w;
            acc[3][0] += a.w * w.x; acc[3][1] += a.w * w.y; acc[3][2] += a.w * w.z; acc[3][3] += a.w * w.w;
        }
        __syncthreads();
    }

    float* gdst = hh ? g_gh : g_gi;
#pragma unroll
    for (int j = 0; j < 4; ++j)
#pragma unroll
        for (int i = 0; i < 4; ++i)
            atomicAdd(&gdst[(R0 + 4 * ty + j) * B + 4 * tx + i], acc[i][j]);
}

// -------------------- K3b2: gate math + nonlinearity -> h_new + colast --------------------
__device__ __forceinline__ float sigmoidf_(float x) { return 1.0f / (1.0f + expf(-x)); }

__global__ void k3b2_gate(const float* __restrict__ h,
                          const float* __restrict__ bih_f, const float* __restrict__ bhh_f,
                          const float* __restrict__ bih_b, const float* __restrict__ bhh_b,
                          float* __restrict__ out)
{
    int idx  = blockIdx.x * 256 + threadIdx.x;
    int b    = idx & 31;
    int j    = (idx >> 5) & 511;
    int cell = idx >> 14;

    const float* bih = cell ? bih_b : bih_f;
    const float* bhh = cell ? bhh_b : bhh_f;
    int Rb = cell * 1536;

    float Gir = g_gi[(Rb +        j) * B + b] + bih[j];
    float Ghr = g_gh[(Rb +        j) * B + b] + bhh[j];
    float Giz = g_gi[(Rb +  512 + j) * B + b] + bih[512 + j];
    float Ghz = g_gh[(Rb +  512 + j) * B + b] + bhh[512 + j];
    float Gin = g_gi[(Rb + 1024 + j) * B + b] + bih[1024 + j];
    float Ghn = g_gh[(Rb + 1024 + j) * B + b] + bhh[1024 + j];

    float hprev = h[(size_t)cell * B * H + b * H + j];
    float r = sigmoidf_(Gir + Ghr);
    float z = sigmoidf_(Giz + Ghz);
    float n = tanhf(Gin + r * Ghn);
    float hn = (1.0f - z) * n + z * hprev;

    out[OUT_HNEW + cell * B * H + b * H + j] = hn;
    if (b == B - 1) g_colast[cell * H + j] = hn;
}

// -------------------- K4: vocab GEMV --------------------
__global__ void k4_logits(const float4* __restrict__ outW, const float* __restrict__ outb)
{
    __shared__ float4 sc[D2H / 4];
    int tid = threadIdx.x;
    sc[tid] = ((const float4*)g_colast)[tid];
    __syncthreads();

    int warp = tid >> 5, lane = tid & 31;
    int v = blockIdx.x * 8 + warp;
    const float4* wrow = outW + (size_t)v * (D2H / 4);
    float acc = 0.f;
#pragma unroll
    for (int i = 0; i < 8; ++i) {
        float4 w = wrow[lane + 32 * i];
        float4 c = sc[lane + 32 * i];
        acc += w.x * c.x + w.y * c.y + w.z * c.z + w.w * c.w;
    }
#pragma unroll
    for (int o = 16; o; o >>= 1) acc += __shfl_xor_sync(0xFFFFFFFFu, acc, o);
    if (lane == 0) g_logits[v] = acc + outb[v];
}

// -------------------- K5a: per-block (max, sumexp) partials --------------------
__global__ void k5a_partial()
{
    const float4* L4 = (const float4*)g_logits;
    int tid = threadIdx.x;
    __shared__ float red[8];

    float m = -1e30f;
    for (int i = blockIdx.x * 256 + tid; i < V / 4; i += 32 * 256) {
        float4 v = L4[i];
        m = fmaxf(m, fmaxf(fmaxf(v.x, v.y), fmaxf(v.z, v.w)));
    }
#pragma unroll
    for (int o = 16; o; o >>= 1) m = fmaxf(m, __shfl_xor_sync(0xFFFFFFFFu, m, o));
    if ((tid & 31) == 0) red[tid >> 5] = m;
    __syncthreads();
    float bm = fmaxf(fmaxf(fmaxf(red[0], red[1]), fmaxf(red[2], red[3])),
                     fmaxf(fmaxf(red[4], red[5]), fmaxf(red[6], red[7])));
    __syncthreads();

    float s = 0.f;
    for (int i = blockIdx.x * 256 + tid; i < V / 4; i += 32 * 256) {
        float4 v = L4[i];
        s += expf(v.x - bm) + expf(v.y - bm) + expf(v.z - bm) + expf(v.w - bm);
    }
#pragma unroll
    for (int o = 16; o; o >>= 1) s += __shfl_xor_sync(0xFFFFFFFFu, s, o);
    if ((tid & 31) == 0) red[tid >> 5] = s;
    __syncthreads();
    if (tid == 0) {
        float bs = red[0] + red[1] + red[2] + red[3] + red[4] + red[5] + red[6] + red[7];
        g_lse[blockIdx.x] = make_float2(bm, bs);
    }
}

// -------------------- K5b: combine partials, write logp --------------------
__global__ void k5b_write(float* __restrict__ out)
{
    float M = -1e30f;
#pragma unroll
    for (int i = 0; i < 32; ++i) M = fmaxf(M, g_lse[i].x);
    float S = 0.f;
#pragma unroll
    for (int i = 0; i < 32; ++i) { float2 p = g_lse[i]; S += p.y * expf(p.x - M); }
    float lse = M + logf(S);

    const float4* L4 = (const float4*)g_logits;
    float4* O4 = (float4*)(out + OUT_LOGP);
    for (int i = blockIdx.x * 256 + threadIdx.x; i < V / 4; i += 32 * 256) {
        float4 v = L4[i];
        v.x -= lse; v.y -= lse; v.z -= lse; v.w -= lse;
        O4[i] = v;
    }
}

// -------------------- launch: single linear chain on stream 0 --------------------
extern "C" void kernel_launch(void* const* d_in, const int* in_sizes, int n_in,
                              void* d_out, int out_size)
{
    (void)in_sizes; (void)n_in; (void)out_size;
    const float* h_in   = (const float*)d_in[1];
    const float* enc    = (const float*)d_in[2];
    const float* Wih_f  = (const float*)d_in[6];
    const float* Whh_f  = (const float*)d_in[7];
    const float* bih_f  = (const float*)d_in[8];
    const float* bhh_f  = (const float*)d_in[9];
    const float* Wih_b  = (const float*)d_in[10];
    const float* Whh_b  = (const float*)d_in[11];
    const float* bih_b  = (const float*)d_in[12];
    const float* bhh_b  = (const float*)d_in[13];
    const float* outW   = (const float*)d_in[14];
    const float* outb   = (const float*)d_in[15];
    float* out = (float*)d_out;

    k0_zero<<<225, 256>>>();
    k1_reduce<<<dim3(SPLITS, B), 256>>>((const float4*)enc, out);
    k3a_gemm<<<48 * KSPL, 128>>>(h_in, Wih_f, Whh_f, Wih_b, Whh_b);
    k3b2_gate<<<(2 * B * H) / 256, 256>>>(h_in, bih_f, bhh_f, bih_b, bhh_b, out);
    k4_logits<<<V / 8, 256>>>((const float4*)outW, outb);
    k5a_partial<<<32, 256>>>();
    k5b_write<<<32, 256>>>(out);
}

// round 15
// speedup vs baseline: 1.0254x; 1.0247x over previous
#include <cuda_runtime.h>
#include <math.h>

// Problem constants
#define B    32
#define L    2048
#define E    512
#define H    512
#define V    32000
#define D2H  1024          // 2*H
#define SPLITS 32          // L split for k1 reduction (64 rows per block)

// Output layout (fp32): logp[32000] | h_new[32768] | attn_weights[65536]
#define OUT_LOGP  0
#define OUT_HNEW  32000
#define OUT_ATTN  64768

// GRU GEMM geometry: rows = 2 cells * 3 gates * 512 = 3072, K = 1024(ih) + 512(hh)
#define NROWS 3072
#define ROWT  64            // rows per block tile
#define KSPL  24            // splits: 0..15 = ih (64 cols each), 16..23 = hh (64 cols each)
#define KPS   64            // K per split

// -------------------- scratch --------------------
__device__ float  g_cacc[D2H * B];       // c accumulator, [k][b] layout (RED from k1)
__device__ float  g_gi[NROWS * B];       // accumulated gi (RED)
__device__ float  g_gh[NROWS * B];       // accumulated gh (RED)
__device__ float  g_colast[D2H];         // [h_f[31], h_b[31]]
__device__ float  g_logits[V];
__device__ float2 g_lse[32];             // per-block (max, sumexp)

// -------------------- K0: zero all RED accumulators --------------------
// g_gi: 24576 float4, g_gh: 24576 float4, g_cacc: 8192 float4  => 57344 float4
__global__ void k0_zero()
{
    int idx = blockIdx.x * 256 + threadIdx.x;          // 225*256 = 57600 threads
    const float4 z = make_float4(0.f, 0.f, 0.f, 0.f);
    if      (idx < 24576) ((float4*)g_gi)[idx]           = z;
    else if (idx < 49152) ((float4*)g_gh)[idx - 24576]   = z;
    else if (idx < 57344) ((float4*)g_cacc)[idx - 49152] = z;
}

// -------------------- K1: reduce encoder_out over L -> atomic c accumulate (+ attn fill) ----
// grid (SPLITS=32, B) = 1024 blocks (~7/SM), 256 threads; each block streams 64 L-rows.
__global__ void k1_reduce(const float4* __restrict__ enc, float* __restrict__ out)
{
    int s = blockIdx.x, b = blockIdx.y, t = threadIdx.x;
    int l0 = s * (L / SPLITS);
    float4 acc = make_float4(0.f, 0.f, 0.f, 0.f);
    const float4* base = enc + (size_t)(b * L + l0) * (D2H / 4) + t;
#pragma unroll 8
    for (int l = 0; l < L / SPLITS; ++l) {
        float4 v = base[(size_t)l * (D2H / 4)];
        acc.x += v.x; acc.y += v.y; acc.z += v.z; acc.w += v.w;
    }
    // accumulate into transposed c accumulator [k][b]
    atomicAdd(&g_cacc[(4 * t + 0) * B + b], acc.x);
    atomicAdd(&g_cacc[(4 * t + 1) * B + b], acc.y);
    atomicAdd(&g_cacc[(4 * t + 2) * B + b], acc.z);
    atomicAdd(&g_cacc[(4 * t + 3) * B + b], acc.w);

    // constant attn_weights fill: 1024 blocks x 16 float4 = 16384 float4
    if (t < 16) {
        int fid = b * SPLITS + s;
        const float w = 1.0f / (float)L;
        ((float4*)(out + OUT_ATTN))[fid * 16 + t] = make_float4(w, w, w, w);
    }
}

// -------------------- K3a: split-K register-tiled GEMM, swizzled smem, RED epilogue ------
// One launch: 48 row-tiles * 24 splits = 1152 blocks, 128 threads.
// ih splits read g_cacc with inline relu(x/L); hh splits read h.
// Swizzle: element (k, col) lives at [k][col ^ (k & 0x1C)].
__global__ void k3a_gemm(const float* __restrict__ h,
                         const float* __restrict__ Wih_f, const float* __restrict__ Whh_f,
                         const float* __restrict__ Wih_b, const float* __restrict__ Whh_b)
{
    int tile  = blockIdx.x / KSPL;
    int split = blockIdx.x % KSPL;
    int R0    = tile * ROWT;
    int cell  = (R0 >= 1536) ? 1 : 0;
    int gr0   = R0 - cell * 1536;

    const bool   hh   = (split >= 16);
    const float* W    = hh ? (cell ? Whh_b : Whh_f) : (cell ? Wih_b : Wih_f);
    const int    ldw  = hh ? H : D2H;
    const int    koff = hh ? (split - 16) * KPS : split * KPS;

    __shared__ float sW[32 * 64];      // [k][row^swz]
    __shared__ float sX[32 * 32];      // [k][b^swz]

    int tid = threadIdx.x;
    int tx  = tid & 7;
    int ty  = tid >> 3;

    float acc[4][4];
#pragma unroll
    for (int i = 0; i < 4; ++i)
#pragma unroll
        for (int j = 0; j < 4; ++j) acc[i][j] = 0.f;

    const float4* H4  = (const float4*)(h + (size_t)cell * B * H);
    const float4* cA4 = (const float4*)g_cacc;
    const float   invL = 1.0f / (float)L;

#pragma unroll
    for (int kt = 0; kt < KPS; kt += 32) {
        // --- W tile: 64 rows x 32 k, swizzled transpose ---
#pragma unroll
        for (int i = 0; i < 4; ++i) {
            int idx = tid + i * 128;
            int row = idx >> 3, kg = idx & 7;
            const float4* wr = (const float4*)(W + (size_t)(gr0 + row) * ldw + koff + kt);
            float4 w = wr[kg];
            int k0 = 4 * kg;
            int c  = row ^ k0;
            sW[(k0 + 0) * 64 + c] = w.x;
            sW[(k0 + 1) * 64 + c] = w.y;
            sW[(k0 + 2) * 64 + c] = w.z;
            sW[(k0 + 3) * 64 + c] = w.w;
        }
        // --- X tile ---
        if (!hh) {
#pragma unroll
            for (int i = 0; i < 2; ++i) {
                int idx = tid + i * 128;
                int k = idx >> 3, bg = idx & 7;
                float4 v = cA4[(size_t)(koff + kt + k) * 8 + bg];
                v.x = fmaxf(v.x * invL, 0.f);
                v.y = fmaxf(v.y * invL, 0.f);
                v.z = fmaxf(v.z * invL, 0.f);
                v.w = fmaxf(v.w * invL, 0.f);
                int s = k & 0x1C;
                *(float4*)&sX[k * 32 + ((4 * bg) ^ s)] = v;
            }
        } else {
#pragma unroll
            for (int i = 0; i < 2; ++i) {
                int idx = tid + i * 128;
                int b = idx >> 3, kg = idx & 7;
                float4 hv = H4[(size_t)b * (H / 4) + ((koff + kt) >> 2) + kg];
                int k0 = 4 * kg;
                int c  = b ^ k0;
                sX[(k0 + 0) * 32 + c] = hv.x;
                sX[(k0 + 1) * 32 + c] = hv.y;
                sX[(k0 + 2) * 32 + c] = hv.z;
                sX[(k0 + 3) * 32 + c] = hv.w;
            }
        }
        __syncthreads();

#pragma unroll
        for (int k = 0; k < 32; ++k) {
            int s = k & 0x1C;
            float4 a = *(const float4*)&sX[k * 32 + ((4 * tx) ^ s)];
            float4 w = *(const float4*)&sW[k * 64 + ((4 * ty) ^ s)];
            acc[0][0] += a.x * w.x; acc[0][1] += a.x * w.y; acc[0][2] += a.x * w.z; acc[0][3] += a.x * w.w;
            acc[1][0] += a.y * w.x; acc[1][1] += a.y * w.y; acc[1][2] += a.y * w.z; acc[1][3] += a.y * w.w;
            acc[2][0] += a.z * w.x; acc[2][1] += a.z * w.y; acc[2][2] += a.z * w.z; acc[2][3] += a.z * w.w;
            acc[3][0] += a.w * w.x; acc[3][1] += a.w * w.y; acc[3][2] += a.w * w.z; acc[3][3] += a.w * w.w;
        }
        __syncthreads();
    }

    float* gdst = hh ? g_gh : g_gi;
#pragma unroll
    for (int j = 0; j < 4; ++j)
#pragma unroll
        for (int i = 0; i < 4; ++i)
            atomicAdd(&gdst[(R0 + 4 * ty + j) * B + 4 * tx + i], acc[i][j]);
}

// -------------------- K3b2: gate math, smem-transposed I/O --------------------
// grid 128 (cell = bid>>6, jt = bid&63), 256 threads.
// Compute phase: lane = b (g-reads coalesced). I/O phase: 8 consecutive j per b
// (h-reads and out-writes 4 sectors/warp instead of 32).
__device__ __forceinline__ float sigmoidf_(float x) { return 1.0f / (1.0f + expf(-x)); }

__global__ void k3b2_gate(const float* __restrict__ h,
                          const float* __restrict__ bih_f, const float* __restrict__ bhh_f,
                          const float* __restrict__ bih_b, const float* __restrict__ bhh_b,
                          float* __restrict__ out)
{
    int tid  = threadIdx.x;
    int cell = blockIdx.x >> 6;
    int jt   = blockIdx.x & 63;        // tile of 8 j-values

    __shared__ float sh[8][33];        // h transposed [jy][b]
    __shared__ float so[8][33];        // hn transposed [jy][b]

    // load h coalesced: thread -> (b = tid>>3, jy = tid&7)
    {
        int b = tid >> 3, jy = tid & 7;
        sh[jy][b] = h[(size_t)cell * B * H + b * H + jt * 8 + jy];
    }
    __syncthreads();

    // compute: thread -> (b = tid&31, jy = tid>>5)
    {
        int b  = tid & 31;
        int jy = tid >> 5;
        int j  = jt * 8 + jy;
        const float* bih = cell ? bih_b : bih_f;
        const float* bhh = cell ? bhh_b : bhh_f;
        int Rb = cell * 1536;

        float Gir = g_gi[(Rb +        j) * B + b] + bih[j];
        float Ghr = g_gh[(Rb +        j) * B + b] + bhh[j];
        float Giz = g_gi[(Rb +  512 + j) * B + b] + bih[512 + j];
        float Ghz = g_gh[(Rb +  512 + j) * B + b] + bhh[512 + j];
        float Gin = g_gi[(Rb + 1024 + j) * B + b] + bih[1024 + j];
        float Ghn = g_gh[(Rb + 1024 + j) * B + b] + bhh[1024 + j];

        float hprev = sh[jy][b];
        float r = sigmoidf_(Gir + Ghr);
        float z = sigmoidf_(Giz + Ghz);
        float n = tanhf(Gin + r * Ghn);
        float hn = (1.0f - z) * n + z * hprev;
        so[jy][b] = hn;
        if (b == B - 1) g_colast[cell * H + j] = hn;
    }
    __syncthreads();

    // store coalesced: thread -> (b = tid>>3, jy = tid&7)
    {
        int b = tid >> 3, jy = tid & 7;
        out[OUT_HNEW + (size_t)cell * B * H + b * H + jt * 8 + jy] = so[jy][b];
    }
}

// -------------------- K4: vocab GEMV --------------------
__global__ void k4_logits(const float4* __restrict__ outW, const float* __restrict__ outb)
{
    __shared__ float4 sc[D2H / 4];
    int tid = threadIdx.x;
    sc[tid] = ((const float4*)g_colast)[tid];
    __syncthreads();

    int warp = tid >> 5, lane = tid & 31;
    int v = blockIdx.x * 8 + warp;
    const float4* wrow = outW + (size_t)v * (D2H / 4);
    float acc = 0.f;
#pragma unroll
    for (int i = 0; i < 8; ++i) {
        float4 w = wrow[lane + 32 * i];
        float4 c = sc[lane + 32 * i];
        acc += w.x * c.x + w.y * c.y + w.z * c.z + w.w * c.w;
    }
#pragma unroll
    for (int o = 16; o; o >>= 1) acc += __shfl_xor_sync(0xFFFFFFFFu, acc, o);
    if (lane == 0) g_logits[v] = acc + outb[v];
}

// -------------------- K5a: per-block (max, sumexp) partials --------------------
__global__ void k5a_partial()
{
    const float4* L4 = (const float4*)g_logits;
    int tid = threadIdx.x;
    __shared__ float red[8];

    float m = -1e30f;
    for (int i = blockIdx.x * 256 + tid; i < V / 4; i += 32 * 256) {
        float4 v = L4[i];
        m = fmaxf(m, fmaxf(fmaxf(v.x, v.y), fmaxf(v.z, v.w)));
    }
#pragma unroll
    for (int o = 16; o; o >>= 1) m = fmaxf(m, __shfl_xor_sync(0xFFFFFFFFu, m, o));
    if ((tid & 31) == 0) red[tid >> 5] = m;
    __syncthreads();
    float bm = fmaxf(fmaxf(fmaxf(red[0], red[1]), fmaxf(red[2], red[3])),
                     fmaxf(fmaxf(red[4], red[5]), fmaxf(red[6], red[7])));
    __syncthreads();

    float s = 0.f;
    for (int i = blockIdx.x * 256 + tid; i < V / 4; i += 32 * 256) {
        float4 v = L4[i];
        s += expf(v.x - bm) + expf(v.y - bm) + expf(v.z - bm) + expf(v.w - bm);
    }
#pragma unroll
    for (int o = 16; o; o >>= 1) s += __shfl_xor_sync(0xFFFFFFFFu, s, o);
    if ((tid & 31) == 0) red[tid >> 5] = s;
    __syncthreads();
    if (tid == 0) {
        float bs = red[0] + red[1] + red[2] + red[3] + red[4] + red[5] + red[6] + red[7];
        g_lse[blockIdx.x] = make_float2(bm, bs);
    }
}

// -------------------- K5b: combine partials, write logp --------------------
__global__ void k5b_write(float* __restrict__ out)
{
    float M = -1e30f;
#pragma unroll
    for (int i = 0; i < 32; ++i) M = fmaxf(M, g_lse[i].x);
    float S = 0.f;
#pragma unroll
    for (int i = 0; i < 32; ++i) { float2 p = g_lse[i]; S += p.y * expf(p.x - M); }
    float lse = M + logf(S);

    const float4* L4 = (const float4*)g_logits;
    float4* O4 = (float4*)(out + OUT_LOGP);
    for (int i = blockIdx.x * 256 + threadIdx.x; i < V / 4; i += 32 * 256) {
        float4 v = L4[i];
        v.x -= lse; v.y -= lse; v.z -= lse; v.w -= lse;
        O4[i] = v;
    }
}

// -------------------- launch: single linear chain on stream 0 --------------------
extern "C" void kernel_launch(void* const* d_in, const int* in_sizes, int n_in,
                              void* d_out, int out_size)
{
    (void)in_sizes; (void)n_in; (void)out_size;
    const float* h_in   = (const float*)d_in[1];
    const float* enc    = (const float*)d_in[2];
    const float* Wih_f  = (const float*)d_in[6];
    const float* Whh_f  = (const float*)d_in[7];
    const float* bih_f  = (const float*)d_in[8];
    const float* bhh_f  = (const float*)d_in[9];
    const float* Wih_b  = (const float*)d_in[10];
    const float* Whh_b  = (const float*)d_in[11];
    const float* bih_b  = (const float*)d_in[12];
    const float* bhh_b  = (const float*)d_in[13];
    const float* outW   = (const float*)d_in[14];
    const float* outb   = (const float*)d_in[15];
    float* out = (float*)d_out;

    k0_zero<<<225, 256>>>();
    k1_reduce<<<dim3(SPLITS, B), 256>>>((const float4*)enc, out);
    k3a_gemm<<<48 * KSPL, 128>>>(h_in, Wih_f, Whh_f, Wih_b, Whh_b);
    k3b2_gate<<<128, 256>>>(h_in, bih_f, bhh_f, bih_b, bhh_b, out);
    k4_logits<<<V / 8, 256>>>((const float4*)outW, outb);
    k5a_partial<<<32, 256>>>();
    k5b_write<<<32, 256>>>(out);
}

// round 16
// speedup vs baseline: 1.0685x; 1.0420x over previous
#include <cuda_runtime.h>
#include <math.h>

// Problem constants
#define B    32
#define L    2048
#define E    512
#define H    512
#define V    32000
#define D2H  1024          // 2*H
#define SPLITS 32          // L split for k1 reduction (64 rows per block)

// Output layout (fp32): logp[32000] | h_new[32768] | attn_weights[65536]
#define OUT_LOGP  0
#define OUT_HNEW  32000
#define OUT_ATTN  64768

// GRU GEMM geometry: rows = 2 cells * 3 gates * 512 = 3072, K = 1024(ih) + 512(hh)
#define NROWS 3072
#define ROWT  64            // rows per block tile
#define KSPL  24            // splits: 0..15 = ih (64 cols each), 16..23 = hh (64 cols each)
#define KPS   64            // K per split

// -------------------- scratch --------------------
__device__ float  g_cacc[D2H * B];       // c accumulator, [k][b] layout (RED from k1)
__device__ float  g_gi[NROWS * B];       // accumulated gi (RED)
__device__ float  g_gh[NROWS * B];       // accumulated gh (RED)
__device__ float  g_colast[D2H];         // [h_f[31], h_b[31]]
__device__ float  g_logits[V];
__device__ float2 g_lse[32];             // per-block (max, sumexp)

// -------------------- K0: zero all RED accumulators --------------------
// g_gi: 24576 float4, g_gh: 24576 float4, g_cacc: 8192 float4  => 57344 float4
__global__ void k0_zero()
{
    int idx = blockIdx.x * 256 + threadIdx.x;          // 225*256 = 57600 threads
    const float4 z = make_float4(0.f, 0.f, 0.f, 0.f);
    if      (idx < 24576) ((float4*)g_gi)[idx]           = z;
    else if (idx < 49152) ((float4*)g_gh)[idx - 24576]   = z;
    else if (idx < 57344) ((float4*)g_cacc)[idx - 49152] = z;
}

// -------------------- K1: reduce encoder_out over L -> atomic c accumulate (+ attn fill) ----
// grid (SPLITS=32, B) = 1024 blocks (~7/SM), 256 threads; each block streams 64 L-rows.
__global__ void k1_reduce(const float4* __restrict__ enc, float* __restrict__ out)
{
    int s = blockIdx.x, b = blockIdx.y, t = threadIdx.x;
    int l0 = s * (L / SPLITS);
    float4 acc = make_float4(0.f, 0.f, 0.f, 0.f);
    const float4* base = enc + (size_t)(b * L + l0) * (D2H / 4) + t;
#pragma unroll 8
    for (int l = 0; l < L / SPLITS; ++l) {
        float4 v = base[(size_t)l * (D2H / 4)];
        acc.x += v.x; acc.y += v.y; acc.z += v.z; acc.w += v.w;
    }
    // accumulate into transposed c accumulator [k][b]
    atomicAdd(&g_cacc[(4 * t + 0) * B + b], acc.x);
    atomicAdd(&g_cacc[(4 * t + 1) * B + b], acc.y);
    atomicAdd(&g_cacc[(4 * t + 2) * B + b], acc.z);
    atomicAdd(&g_cacc[(4 * t + 3) * B + b], acc.w);

    // constant attn_weights fill: 1024 blocks x 16 float4 = 16384 float4
    if (t < 16) {
        int fid = b * SPLITS + s;
        const float w = 1.0f / (float)L;
        ((float4*)(out + OUT_ATTN))[fid * 16 + t] = make_float4(w, w, w, w);
    }
}

// -------------------- K3a: split-K register-tiled GEMM, swizzled smem, RED.v4 epilogue ----
// One launch: 48 row-tiles * 24 splits = 1152 blocks, 128 threads.
// ih splits read g_cacc with inline relu(x/L); hh splits read h.
// Swizzle: element (k, col) lives at [k][col ^ (k & 0x1C)].
__global__ void k3a_gemm(const float* __restrict__ h,
                         const float* __restrict__ Wih_f, const float* __restrict__ Whh_f,
                         const float* __restrict__ Wih_b, const float* __restrict__ Whh_b)
{
    int tile  = blockIdx.x / KSPL;
    int split = blockIdx.x % KSPL;
    int R0    = tile * ROWT;
    int cell  = (R0 >= 1536) ? 1 : 0;
    int gr0   = R0 - cell * 1536;

    const bool   hh   = (split >= 16);
    const float* W    = hh ? (cell ? Whh_b : Whh_f) : (cell ? Wih_b : Wih_f);
    const int    ldw  = hh ? H : D2H;
    const int    koff = hh ? (split - 16) * KPS : split * KPS;

    __shared__ float sW[32 * 64];      // [k][row^swz]
    __shared__ float sX[32 * 32];      // [k][b^swz]

    int tid = threadIdx.x;
    int tx  = tid & 7;
    int ty  = tid >> 3;

    float acc[4][4];
#pragma unroll
    for (int i = 0; i < 4; ++i)
#pragma unroll
        for (int j = 0; j < 4; ++j) acc[i][j] = 0.f;

    const float4* H4  = (const float4*)(h + (size_t)cell * B * H);
    const float4* cA4 = (const float4*)g_cacc;
    const float   invL = 1.0f / (float)L;

#pragma unroll
    for (int kt = 0; kt < KPS; kt += 32) {
        // --- W tile: 64 rows x 32 k, swizzled transpose ---
#pragma unroll
        for (int i = 0; i < 4; ++i) {
            int idx = tid + i * 128;
            int row = idx >> 3, kg = idx & 7;
            const float4* wr = (const float4*)(W + (size_t)(gr0 + row) * ldw + koff + kt);
            float4 w = wr[kg];
            int k0 = 4 * kg;
            int c  = row ^ k0;
            sW[(k0 + 0) * 64 + c] = w.x;
            sW[(k0 + 1) * 64 + c] = w.y;
            sW[(k0 + 2) * 64 + c] = w.z;
            sW[(k0 + 3) * 64 + c] = w.w;
        }
        // --- X tile ---
        if (!hh) {
#pragma unroll
            for (int i = 0; i < 2; ++i) {
                int idx = tid + i * 128;
                int k = idx >> 3, bg = idx & 7;
                float4 v = cA4[(size_t)(koff + kt + k) * 8 + bg];
                v.x = fmaxf(v.x * invL, 0.f);
                v.y = fmaxf(v.y * invL, 0.f);
                v.z = fmaxf(v.z * invL, 0.f);
                v.w = fmaxf(v.w * invL, 0.f);
                int s = k & 0x1C;
                *(float4*)&sX[k * 32 + ((4 * bg) ^ s)] = v;
            }
        } else {
#pragma unroll
            for (int i = 0; i < 2; ++i) {
                int idx = tid + i * 128;
                int b = idx >> 3, kg = idx & 7;
                float4 hv = H4[(size_t)b * (H / 4) + ((koff + kt) >> 2) + kg];
                int k0 = 4 * kg;
                int c  = b ^ k0;
                sX[(k0 + 0) * 32 + c] = hv.x;
                sX[(k0 + 1) * 32 + c] = hv.y;
                sX[(k0 + 2) * 32 + c] = hv.z;
                sX[(k0 + 3) * 32 + c] = hv.w;
            }
        }
        __syncthreads();

#pragma unroll
        for (int k = 0; k < 32; ++k) {
            int s = k & 0x1C;
            float4 a = *(const float4*)&sX[k * 32 + ((4 * tx) ^ s)];
            float4 w = *(const float4*)&sW[k * 64 + ((4 * ty) ^ s)];
            acc[0][0] += a.x * w.x; acc[0][1] += a.x * w.y; acc[0][2] += a.x * w.z; acc[0][3] += a.x * w.w;
            acc[1][0] += a.y * w.x; acc[1][1] += a.y * w.y; acc[1][2] += a.y * w.z; acc[1][3] += a.y * w.w;
            acc[2][0] += a.z * w.x; acc[2][1] += a.z * w.y; acc[2][2] += a.z * w.z; acc[2][3] += a.z * w.w;
            acc[3][0] += a.w * w.x; acc[3][1] += a.w * w.y; acc[3][2] += a.w * w.z; acc[3][3] += a.w * w.w;
        }
        __syncthreads();
    }

    // RED.v4 epilogue: acc[0..3][j] hit 4 consecutive floats (batch 4tx..4tx+3)
    float* gdst = hh ? g_gh : g_gi;
#pragma unroll
    for (int j = 0; j < 4; ++j) {
        float* p = &gdst[(size_t)(R0 + 4 * ty + j) * B + 4 * tx];
        asm volatile("red.global.add.v4.f32 [%0], {%1, %2, %3, %4};"
                     :: "l"(p), "f"(acc[0][j]), "f"(acc[1][j]),
                        "f"(acc[2][j]), "f"(acc[3][j])
                     : "memory");
    }
}

// -------------------- K3b2: gate math, smem-transposed I/O --------------------
// grid 256 (cell = bid>>7, jt = bid&127 -> 4 j-values), 128 threads.
__device__ __forceinline__ float sigmoidf_(float x) { return 1.0f / (1.0f + expf(-x)); }

__global__ void k3b2_gate(const float* __restrict__ h,
                          const float* __restrict__ bih_f, const float* __restrict__ bhh_f,
                          const float* __restrict__ bih_b, const float* __restrict__ bhh_b,
                          float* __restrict__ out)
{
    int tid  = threadIdx.x;
    int cell = blockIdx.x >> 7;
    int jt   = blockIdx.x & 127;       // tile of 4 j-values

    __shared__ float sh[4][33];        // h transposed [jy][b]
    __shared__ float so[4][33];        // hn transposed [jy][b]

    // load h coalesced: thread -> (b = tid>>2, jy = tid&3)
    {
        int b = tid >> 2, jy = tid & 3;
        sh[jy][b] = h[(size_t)cell * B * H + b * H + jt * 4 + jy];
    }
    __syncthreads();

    // compute: thread -> (b = tid&31, jy = tid>>5)
    {
        int b  = tid & 31;
        int jy = tid >> 5;
        int j  = jt * 4 + jy;
        const float* bih = cell ? bih_b : bih_f;
        const float* bhh = cell ? bhh_b : bhh_f;
        int Rb = cell * 1536;

        float Gir = g_gi[(Rb +        j) * B + b] + bih[j];
        float Ghr = g_gh[(Rb +        j) * B + b] + bhh[j];
        float Giz = g_gi[(Rb +  512 + j) * B + b] + bih[512 + j];
        float Ghz = g_gh[(Rb +  512 + j) * B + b] + bhh[512 + j];
        float Gin = g_gi[(Rb + 1024 + j) * B + b] + bih[1024 + j];
        float Ghn = g_gh[(Rb + 1024 + j) * B + b] + bhh[1024 + j];

        float hprev = sh[jy][b];
        float r = sigmoidf_(Gir + Ghr);
        float z = sigmoidf_(Giz + Ghz);
        float n = tanhf(Gin + r * Ghn);
        float hn = (1.0f - z) * n + z * hprev;
        so[jy][b] = hn;
        if (b == B - 1) g_colast[cell * H + j] = hn;
    }
    __syncthreads();

    // store coalesced: thread -> (b = tid>>2, jy = tid&3)
    {
        int b = tid >> 2, jy = tid & 3;
        out[OUT_HNEW + (size_t)cell * B * H + b * H + jt * 4 + jy] = so[jy][b];
    }
}

// -------------------- K4: vocab GEMV --------------------
__global__ void k4_logits(const float4* __restrict__ outW, const float* __restrict__ outb)
{
    __shared__ float4 sc[D2H / 4];
    int tid = threadIdx.x;
    sc[tid] = ((const float4*)g_colast)[tid];
    __syncthreads();

    int warp = tid >> 5, lane = tid & 31;
    int v = blockIdx.x * 8 + warp;
    const float4* wrow = outW + (size_t)v * (D2H / 4);
    float acc = 0.f;
#pragma unroll
    for (int i = 0; i < 8; ++i) {
        float4 w = wrow[lane + 32 * i];
        float4 c = sc[lane + 32 * i];
        acc += w.x * c.x + w.y * c.y + w.z * c.z + w.w * c.w;
    }
#pragma unroll
    for (int o = 16; o; o >>= 1) acc += __shfl_xor_sync(0xFFFFFFFFu, acc, o);
    if (lane == 0) g_logits[v] = acc + outb[v];
}

// -------------------- K5a: per-block (max, sumexp) partials --------------------
__global__ void k5a_partial()
{
    const float4* L4 = (const float4*)g_logits;
    int tid = threadIdx.x;
    __shared__ float red[8];

    float m = -1e30f;
    for (int i = blockIdx.x * 256 + tid; i < V / 4; i += 32 * 256) {
        float4 v = L4[i];
        m = fmaxf(m, fmaxf(fmaxf(v.x, v.y), fmaxf(v.z, v.w)));
    }
#pragma unroll
    for (int o = 16; o; o >>= 1) m = fmaxf(m, __shfl_xor_sync(0xFFFFFFFFu, m, o));
    if ((tid & 31) == 0) red[tid >> 5] = m;
    __syncthreads();
    float bm = fmaxf(fmaxf(fmaxf(red[0], red[1]), fmaxf(red[2], red[3])),
                     fmaxf(fmaxf(red[4], red[5]), fmaxf(red[6], red[7])));
    __syncthreads();

    float s = 0.f;
    for (int i = blockIdx.x * 256 + tid; i < V / 4; i += 32 * 256) {
        float4 v = L4[i];
        s += expf(v.x - bm) + expf(v.y - bm) + expf(v.z - bm) + expf(v.w - bm);
    }
#pragma unroll
    for (int o = 16; o; o >>= 1) s += __shfl_xor_sync(0xFFFFFFFFu, s, o);
    if ((tid & 31) == 0) red[tid >> 5] = s;
    __syncthreads();
    if (tid == 0) {
        float bs = red[0] + red[1] + red[2] + red[3] + red[4] + red[5] + red[6] + red[7];
        g_lse[blockIdx.x] = make_float2(bm, bs);
    }
}

// -------------------- K5b: combine partials, write logp --------------------
__global__ void k5b_write(float* __restrict__ out)
{
    float M = -1e30f;
#pragma unroll
    for (int i = 0; i < 32; ++i) M = fmaxf(M, g_lse[i].x);
    float S = 0.f;
#pragma unroll
    for (int i = 0; i < 32; ++i) { float2 p = g_lse[i]; S += p.y * expf(p.x - M); }
    float lse = M + logf(S);

    const float4* L4 = (const float4*)g_logits;
    float4* O4 = (float4*)(out + OUT_LOGP);
    for (int i = blockIdx.x * 256 + threadIdx.x; i < V / 4; i += 32 * 256) {
        float4 v = L4[i];
        v.x -= lse; v.y -= lse; v.z -= lse; v.w -= lse;
        O4[i] = v;
    }
}

// -------------------- launch: single linear chain on stream 0 --------------------
extern "C" void kernel_launch(void* const* d_in, const int* in_sizes, int n_in,
                              void* d_out, int out_size)
{
    (void)in_sizes; (void)n_in; (void)out_size;
    const float* h_in   = (const float*)d_in[1];
    const float* enc    = (const float*)d_in[2];
    const float* Wih_f  = (const float*)d_in[6];
    const float* Whh_f  = (const float*)d_in[7];
    const float* bih_f  = (const float*)d_in[8];
    const float* bhh_f  = (const float*)d_in[9];
    const float* Wih_b  = (const float*)d_in[10];
    const float* Whh_b  = (const float*)d_in[11];
    const float* bih_b  = (const float*)d_in[12];
    const float* bhh_b  = (const float*)d_in[13];
    const float* outW   = (const float*)d_in[14];
    const float* outb   = (const float*)d_in[15];
    float* out = (float*)d_out;

    k0_zero<<<225, 256>>>();
    k1_reduce<<<dim3(SPLITS, B), 256>>>((const float4*)enc, out);
    k3a_gemm<<<48 * KSPL, 128>>>(h_in, Wih_f, Whh_f, Wih_b, Whh_b);
    k3b2_gate<<<256, 128>>>(h_in, bih_f, bhh_f, bih_b, bhh_b, out);
    k4_logits<<<V / 8, 256>>>((const float4*)outW, outb);
    k5a_partial<<<32, 256>>>();
    k5b_write<<<32, 256>>>(out);
}